// round 14
// baseline (speedup 1.0000x reference)
#include <cuda_runtime.h>
#include <cuda_fp16.h>
#include <cstdint>

#define D 768
#define NROWS 32768
#define NCODES 8192
#define EPSF 1e-6f

// ---- GEMM tiling (fp16 operands, fp32 accumulate) ----
#define CTAM 256
#define CTAN 128
#define KCH 64                  // halfs per k-chunk = 4 m16n8k16 steps
#define NK16 (KCH / 16)         // 4
#define NCHUNK (D / KCH)        // 12
#define NITER (NCODES / CTAN)   // 64
#define TOTALC (NITER * NCHUNK) // 768 flat chunks
#define PADK 36                 // row stride in half2 units; (l4*36+lc) mod 32 all-distinct
#define A_BYTES (CTAM * PADK * 4)       // 36864
#define B_BYTES (CTAN * PADK * 4)       // 18432
#define STAGE_BYTES (A_BYTES + B_BYTES) // 55296
#define NSTG 3
#define SMEM_DYN (NSTG * STAGE_BYTES)   // 165888
#define NCAND 16                // 8 contributing threads per row x top-2 each
#define GAP_SAFE 0.75f          // >> 2x max fp16 distance error (~0.34)

// ---------------- device scratch (no allocations allowed) ----------------
__device__ __align__(256) __half g_Zh[NROWS * D];   // fp16-rounded z
__device__ __align__(256) __half g_Eh[NCODES * D];  // fp16-rounded emb
__device__ float g_en2[NCODES];
__device__ int   g_cand[NROWS * NCAND];
__device__ float g_cval[NROWS * NCAND];
__device__ float g_partial[NROWS / 8];

// ---------------- helpers ----------------
__device__ __forceinline__ uint32_t smem_u32(const void* p) {
    uint32_t a;
    asm("{ .reg .u64 t; cvta.to.shared.u64 t, %1; cvt.u32.u64 %0, t; }" : "=r"(a) : "l"(p));
    return a;
}
__device__ __forceinline__ void cp16(uint32_t dst, const void* src) {
    asm volatile("cp.async.cg.shared.global [%0], [%1], 16;" :: "r"(dst), "l"(src));
}
#define CP_COMMIT() asm volatile("cp.async.commit_group;")
#define CP_WAIT1()  asm volatile("cp.async.wait_group 1;")

__device__ __forceinline__ void mma_f16(float* c, const uint32_t* a, const uint32_t* b) {
    asm volatile(
        "mma.sync.aligned.m16n8k16.row.col.f32.f16.f16.f32 "
        "{%0,%1,%2,%3}, {%4,%5,%6,%7}, {%8,%9}, {%0,%1,%2,%3};"
        : "+f"(c[0]), "+f"(c[1]), "+f"(c[2]), "+f"(c[3])
        : "r"(a[0]), "r"(a[1]), "r"(a[2]), "r"(a[3]), "r"(b[0]), "r"(b[1]));
}

// ---------------- kernel 0: fp16 rounding of both operands ----------------
__global__ void k_split(const float4* __restrict__ z, const float4* __restrict__ e,
                        int nz4, int ne4) {
    __half2* zh = (__half2*)g_Zh;
    __half2* eh = (__half2*)g_Eh;
    for (int i = blockIdx.x * blockDim.x + threadIdx.x; i < nz4; i += gridDim.x * blockDim.x) {
        float4 v = z[i];
        zh[2 * i]     = __floats2half2_rn(v.x, v.y);
        zh[2 * i + 1] = __floats2half2_rn(v.z, v.w);
        if (i < ne4) {
            float4 w = e[i];
            eh[2 * i]     = __floats2half2_rn(w.x, w.y);
            eh[2 * i + 1] = __floats2half2_rn(w.z, w.w);
        }
    }
}

// ---------------- kernel 1: per-code squared norms (exact fp32) ----------------
__global__ void k_en2(const float* __restrict__ emb, int ncodes) {
    int code = blockIdx.x * 8 + (threadIdx.x >> 5);
    int lane = threadIdx.x & 31;
    if (code >= ncodes) return;
    const float* e = emb + (size_t)code * D;
    float s = 0.f;
#pragma unroll
    for (int j = 0; j < D / 32; j++) { float v = e[lane + 32 * j]; s = fmaf(v, v, s); }
#pragma unroll
    for (int o = 16; o; o >>= 1) s += __shfl_xor_sync(0xffffffffu, s, o);
    if (lane == 0) g_en2[code] = s;
}

// ---------------- kernel 2: fp16 mma.sync distance GEMM + top-2 candidates ----------------
// approx dist(m,n) = ||e_n||^2 - 2 * zh_m . eh_n   (||z||^2 constant per row -> dropped)
__global__ __launch_bounds__(256, 1)
void k_gemm() {
    extern __shared__ __align__(16) char smem[];
    const uint32_t sbase = smem_u32(smem);

    const int tid = threadIdx.x;
    const int wid = tid >> 5;
    const int lane = tid & 31;
    const int m0 = blockIdx.x * CTAM;
    const int wm = (wid & 3) * 64;   // warp M offset
    const int nh = wid >> 2;         // N-half 0/1
    const int wn = nh * 64;          // warp N offset
    const int l4 = lane >> 2;        // groupID 0..7
    const int lc = lane & 3;         // tid-in-group 0..3

    const __half* gZ = g_Zh;
    const __half* gE = g_Eh;

    // candidate lists: 8 rows per thread (4 m-tiles x 2 halves), top-2 each
    float cv0[8], cv1[8];
    int   ci0[8], ci1[8];
#pragma unroll
    for (int r = 0; r < 8; r++) { cv0[r] = 3.4e38f; cv1[r] = 3.4e38f; ci0[r] = 0; ci1[r] = 0; }

    // fragment base offsets (half2 units)
    const int aoff = (wm + l4) * PADK + lc;
    const int boff = (wn + l4) * PADK + lc;

    // flat-chunk loader; ALWAYS commits exactly one group
    auto load_chunk = [&](int tc, int stage) {
        if (tc < TOTALC) {
            const int kc = (tc % NCHUNK) * KCH;     // in halfs
            const int n0 = (tc / NCHUNK) * CTAN;
            const uint32_t st = sbase + stage * STAGE_BYTES;
#pragma unroll
            for (int i = 0; i < 8; i++) {      // A: 256 rows x 128B = 2048 x16B
                int idx = tid + i * 256, row = idx >> 3, seg = idx & 7;
                cp16(st + row * (PADK * 4) + seg * 16,
                     gZ + (size_t)(m0 + row) * D + kc + seg * 8);
            }
#pragma unroll
            for (int i = 0; i < 4; i++) {      // B: 128 rows x 128B = 1024 x16B
                int idx = tid + i * 256, row = idx >> 3, seg = idx & 7;
                cp16(st + A_BYTES + row * (PADK * 4) + seg * 16,
                     gE + (size_t)(n0 + row) * D + kc + seg * 8);
            }
        }
        CP_COMMIT();
    };

    // prologue: chunks 0,1 -> stages 0,1
    load_chunk(0, 0);
    load_chunk(1, 1);

    float acc[4][8][4];
#pragma unroll
    for (int mt = 0; mt < 4; mt++)
#pragma unroll
        for (int nt = 0; nt < 8; nt++)
#pragma unroll
            for (int q = 0; q < 4; q++) acc[mt][nt][q] = 0.f;

    for (int tc = 0; tc < TOTALC; tc++) {
        CP_WAIT1();                 // chunk tc landed (all but newest group done)
        __syncthreads();            // visible CTA-wide + prev stage consumers done

        load_chunk(tc + 2, (tc + 2) % NSTG);

        const uint32_t* As = (const uint32_t*)(smem + (tc % NSTG) * STAGE_BYTES);
        const uint32_t* Bs = (const uint32_t*)(smem + (tc % NSTG) * STAGE_BYTES + A_BYTES);
#pragma unroll
        for (int ks = 0; ks < NK16; ks++) {
            uint32_t af[4][4], bf[8][2];
#pragma unroll
            for (int mt = 0; mt < 4; mt++) {
                int b = aoff + mt * (16 * PADK) + ks * 8;
                af[mt][0] = As[b];                 // (row g,    k 2lc..2lc+1)
                af[mt][1] = As[b + 8 * PADK];      // (row g+8,  same k)
                af[mt][2] = As[b + 4];             // (row g,    k+8)
                af[mt][3] = As[b + 8 * PADK + 4];  // (row g+8,  k+8)
            }
#pragma unroll
            for (int nt = 0; nt < 8; nt++) {
                int b = boff + nt * (8 * PADK) + ks * 8;
                bf[nt][0] = Bs[b];                 // (col g, k 2lc..2lc+1)
                bf[nt][1] = Bs[b + 4];             // (col g, k+8)
            }
#pragma unroll
            for (int mt = 0; mt < 4; mt++)
#pragma unroll
                for (int nt = 0; nt < 8; nt++)
                    mma_f16(acc[mt][nt], af[mt], bf[nt]);
        }

        // ---- iteration boundary: fold 128-code tile into per-row top-2 ----
        if ((tc % NCHUNK) == NCHUNK - 1) {
            const int n0 = (tc / NCHUNK) * CTAN;
#pragma unroll
            for (int mt = 0; mt < 4; mt++) {
#pragma unroll
                for (int h = 0; h < 2; h++) {
                    const int r = mt * 2 + h;
#pragma unroll
                    for (int nt = 0; nt < 8; nt++) {
#pragma unroll
                        for (int q = 0; q < 2; q++) {
                            int nl = wn + nt * 8 + 2 * lc + q;
                            int n = n0 + nl;
                            float dist = fmaf(-2.f, acc[mt][nt][h * 2 + q], __ldg(&g_en2[n]));
                            if (dist < cv1[r]) {
                                if (dist < cv0[r]) {
                                    cv1[r] = cv0[r]; ci1[r] = ci0[r];
                                    cv0[r] = dist;   ci0[r] = n;
                                } else {
                                    cv1[r] = dist;   ci1[r] = n;
                                }
                            }
                            acc[mt][nt][h * 2 + q] = 0.f;   // reset for next tile
                        }
                    }
                }
            }
        }
    }

    // ---- write candidates + values: 16 per row; slot = n_half*8 + lc*2 (+1) ----
#pragma unroll
    for (int mt = 0; mt < 4; mt++) {
#pragma unroll
        for (int h = 0; h < 2; h++) {
            int r = mt * 2 + h;
            int grow = m0 + wm + mt * 16 + l4 + h * 8;
            int slot = nh * 8 + lc * 2;
            g_cand[(size_t)grow * NCAND + slot + 0] = ci0[r];
            g_cand[(size_t)grow * NCAND + slot + 1] = ci1[r];
            g_cval[(size_t)grow * NCAND + slot + 0] = cv0[r];
            g_cval[(size_t)grow * NCAND + slot + 1] = cv1[r];
        }
    }
}

// ---------------- kernel 3: gap-gated rescore + rotation + loss partials ----------------
__global__ void k_rotate(const float* __restrict__ z, const float* __restrict__ emb,
                         float* __restrict__ out, int nrows) {
    __shared__ float s_loss[8];
    int warp = threadIdx.x >> 5;
    int lane = threadIdx.x & 31;
    int row = blockIdx.x * 8 + warp;
    float loss_w = 0.f;

    if (row < nrows) {
        const float* zr = z + (size_t)row * D;
        float zv[D / 32];
        float zz = 0.f;
#pragma unroll
        for (int j = 0; j < D / 32; j++) {
            zv[j] = zr[lane + 32 * j];
            zz = fmaf(zv[j], zv[j], zz);
        }
#pragma unroll
        for (int o = 16; o; o >>= 1) zz += __shfl_xor_sync(0xffffffffu, zz, o);

        // ---- load 16 (value, index) candidate pairs; find approx best & 2nd ----
        float mycv = 3.4e38f;
        int myci = 0;
        if (lane < NCAND) {
            mycv = g_cval[(size_t)row * NCAND + lane];
            myci = g_cand[(size_t)row * NCAND + lane] & (NCODES - 1);
        }
        // warp-reduce min (value, then index for deterministic tie)
        float bv = mycv; int bi = myci;
#pragma unroll
        for (int o = 16; o; o >>= 1) {
            float ov = __shfl_xor_sync(0xffffffffu, bv, o);
            int   oi = __shfl_xor_sync(0xffffffffu, bi, o);
            if (ov < bv || (ov == bv && oi < bi)) { bv = ov; bi = oi; }
        }
        // 2nd best: exclude the winner's slot
        float sv = (mycv == bv && myci == bi) ? 3.4e38f : mycv;
#pragma unroll
        for (int o = 16; o; o >>= 1) {
            float ov = __shfl_xor_sync(0xffffffffu, sv, o);
            sv = fminf(sv, ov);
        }

        int best_i;
        if (sv - bv >= GAP_SAFE) {
            // approx gap large vs fp16 error bound -> approx argmin == exact argmin
            best_i = bi;
        } else {
            // rare path: exact fp32 rescore of all 16
            float best_key = 3.4e38f;
            int bidx = 0x7fffffff;
            for (int c = 0; c < NCAND; c++) {
                int ci = g_cand[(size_t)row * NCAND + c] & (NCODES - 1);
                const float* er = emb + (size_t)ci * D;
                float ze = 0.f;
#pragma unroll
                for (int j = 0; j < D / 32; j++) ze = fmaf(zv[j], er[lane + 32 * j], ze);
#pragma unroll
                for (int o = 16; o; o >>= 1) ze += __shfl_xor_sync(0xffffffffu, ze, o);
                float key = fmaf(-2.f, ze, g_en2[ci]);
                if (key < best_key || (key == best_key && ci < bidx)) { best_key = key; bidx = ci; }
            }
            best_i = bidx;
        }

        // load chosen code, exact stats
        const float* er = emb + (size_t)best_i * D;
        float ev[D / 32];
        float ee = 0.f, ze = 0.f;
#pragma unroll
        for (int j = 0; j < D / 32; j++) {
            ev[j] = er[lane + 32 * j];
            ee = fmaf(ev[j], ev[j], ee);
            ze = fmaf(zv[j], ev[j], ze);
        }
#pragma unroll
        for (int o = 16; o; o >>= 1) {
            ee += __shfl_xor_sync(0xffffffffu, ee, o);
            ze += __shfl_xor_sync(0xffffffffu, ze, o);
        }

        float ns_r = sqrtf(zz), nt_r = sqrtf(ee);
        float ns = fmaxf(ns_r, EPSF), nt = fmaxf(nt_r, EPSF);
        float dot_eu = zz / ns;
        float w2 = zz / (ns * ns) + ee / (nt * nt) + 2.f * ze / (ns * nt);
        float nw = fmaxf(sqrtf(w2), EPSF);
        float dot_ew = (dot_eu + ze / nt) / nw;
        float scale = nt_r / ns;
        float A = scale * (1.f - 2.f * dot_ew / (ns * nw));
        float B = scale * 2.f * (dot_eu - dot_ew / nw) / nt;

        float* orow = out + (size_t)row * D;
#pragma unroll
        for (int j = 0; j < D / 32; j++)
            orow[lane + 32 * j] = fmaf(A, zv[j], B * ev[j]);

        loss_w = zz + ee - 2.f * ze;
    }

    if (lane == 0) s_loss[warp] = loss_w;
    __syncthreads();
    if (threadIdx.x == 0) {
        float s = 0.f;
#pragma unroll
        for (int w = 0; w < 8; w++) s += s_loss[w];
        g_partial[blockIdx.x] = s;
    }
}

// ---------------- kernel 4: finalize scalar loss ----------------
__global__ void k_loss(float* __restrict__ out, int nparts, float inv_count, long long pos) {
    __shared__ float sm[256];
    float s = 0.f;
    for (int i = threadIdx.x; i < nparts; i += 256) s += g_partial[i];
    sm[threadIdx.x] = s;
    __syncthreads();
    for (int o = 128; o; o >>= 1) {
        if (threadIdx.x < o) sm[threadIdx.x] += sm[threadIdx.x + o];
        __syncthreads();
    }
    if (threadIdx.x == 0) out[pos] = 2.f * sm[0] * inv_count;
}

// ---------------- launch ----------------
extern "C" void kernel_launch(void* const* d_in, const int* in_sizes, int n_in,
                              void* d_out, int out_size) {
    const float* z   = (const float*)d_in[0];
    const float* emb = (const float*)d_in[1];
    float* out = (float*)d_out;

    int nrows  = in_sizes[0] / D;    // 32768
    int ncodes = in_sizes[1] / D;    // 8192

    cudaFuncSetAttribute(k_gemm, cudaFuncAttributeMaxDynamicSharedMemorySize, SMEM_DYN);

    int nz4 = nrows * D / 4, ne4 = ncodes * D / 4;
    k_split<<<4096, 256>>>((const float4*)z, (const float4*)emb, nz4, ne4);
    k_en2<<<(ncodes + 7) / 8, 256>>>(emb, ncodes);
    k_gemm<<<nrows / CTAM, 256, SMEM_DYN>>>();
    k_rotate<<<nrows / 8, 256>>>(z, emb, out, nrows);

    long long zq_elems = (long long)nrows * D;
    long long loss_pos = (out_size > zq_elems) ? zq_elems : (long long)out_size - 1;
    k_loss<<<1, 256>>>(out, nrows / 8, 1.f / ((float)nrows * (float)D), loss_pos);
}

// round 15
// speedup vs baseline: 1.5575x; 1.5575x over previous
#include <cuda_runtime.h>
#include <cuda_fp16.h>
#include <cstdint>

#define D 768
#define NROWS 32768
#define NCODES 8192
#define EPSF 1e-6f

// ---- GEMM tiling (fp16 operands, fp32 accumulate) ----
#define CTAM 256
#define CTAN 128
#define KCH 64                  // halfs per k-chunk = 4 m16n8k16 steps
#define NK16 (KCH / 16)         // 4
#define NCHUNK (D / KCH)        // 12
#define NITER (NCODES / CTAN)   // 64
#define TOTALC (NITER * NCHUNK) // 768 flat chunks
#define PADK 36                 // row stride in half2 units; (l4*36+lc) mod 32 all-distinct
#define A_BYTES (CTAM * PADK * 4)       // 36864
#define B_BYTES (CTAN * PADK * 4)       // 18432
#define STAGE_BYTES (A_BYTES + B_BYTES) // 55296
#define NSTG 3
#define SMEM_DYN (NSTG * STAGE_BYTES)   // 165888
#define NCAND 16                // 8 contributing threads per row x top-2 each
#define GAP_SAFE 0.75f          // >> 2x max fp16 distance error (~0.34)

// ---------------- device scratch (no allocations allowed) ----------------
__device__ __align__(256) __half g_Zh[NROWS * D];   // fp16-rounded z
__device__ __align__(256) __half g_Eh[NCODES * D];  // fp16-rounded emb
__device__ float g_en2[NCODES];
__device__ __align__(256) uint4 g_cc[NROWS * 8];    // per row: 8 x {ci0, ci1, cv0, cv1}
__device__ float g_partial[NROWS / 8];

// ---------------- helpers ----------------
__device__ __forceinline__ uint32_t smem_u32(const void* p) {
    uint32_t a;
    asm("{ .reg .u64 t; cvta.to.shared.u64 t, %1; cvt.u32.u64 %0, t; }" : "=r"(a) : "l"(p));
    return a;
}
__device__ __forceinline__ void cp16(uint32_t dst, const void* src) {
    asm volatile("cp.async.cg.shared.global [%0], [%1], 16;" :: "r"(dst), "l"(src));
}
#define CP_COMMIT() asm volatile("cp.async.commit_group;")
#define CP_WAIT1()  asm volatile("cp.async.wait_group 1;")

__device__ __forceinline__ void mma_f16(float* c, const uint32_t* a, const uint32_t* b) {
    asm volatile(
        "mma.sync.aligned.m16n8k16.row.col.f32.f16.f16.f32 "
        "{%0,%1,%2,%3}, {%4,%5,%6,%7}, {%8,%9}, {%0,%1,%2,%3};"
        : "+f"(c[0]), "+f"(c[1]), "+f"(c[2]), "+f"(c[3])
        : "r"(a[0]), "r"(a[1]), "r"(a[2]), "r"(a[3]), "r"(b[0]), "r"(b[1]));
}

// ---------------- kernel 0: fp16 rounding of both operands ----------------
__global__ void k_split(const float4* __restrict__ z, const float4* __restrict__ e,
                        int nz4, int ne4) {
    __half2* zh = (__half2*)g_Zh;
    __half2* eh = (__half2*)g_Eh;
    for (int i = blockIdx.x * blockDim.x + threadIdx.x; i < nz4; i += gridDim.x * blockDim.x) {
        float4 v = z[i];
        zh[2 * i]     = __floats2half2_rn(v.x, v.y);
        zh[2 * i + 1] = __floats2half2_rn(v.z, v.w);
        if (i < ne4) {
            float4 w = e[i];
            eh[2 * i]     = __floats2half2_rn(w.x, w.y);
            eh[2 * i + 1] = __floats2half2_rn(w.z, w.w);
        }
    }
}

// ---------------- kernel 1: per-code squared norms (exact fp32) ----------------
__global__ void k_en2(const float* __restrict__ emb, int ncodes) {
    int code = blockIdx.x * 8 + (threadIdx.x >> 5);
    int lane = threadIdx.x & 31;
    if (code >= ncodes) return;
    const float* e = emb + (size_t)code * D;
    float s = 0.f;
#pragma unroll
    for (int j = 0; j < D / 32; j++) { float v = e[lane + 32 * j]; s = fmaf(v, v, s); }
#pragma unroll
    for (int o = 16; o; o >>= 1) s += __shfl_xor_sync(0xffffffffu, s, o);
    if (lane == 0) g_en2[code] = s;
}

// ---------------- kernel 2: fp16 mma.sync distance GEMM + top-2 candidates ----------------
// approx dist(m,n) = ||e_n||^2 - 2 * zh_m . eh_n   (||z||^2 constant per row -> dropped)
__global__ __launch_bounds__(256, 1)
void k_gemm() {
    extern __shared__ __align__(16) char smem[];
    const uint32_t sbase = smem_u32(smem);

    const int tid = threadIdx.x;
    const int wid = tid >> 5;
    const int lane = tid & 31;
    const int m0 = blockIdx.x * CTAM;
    const int wm = (wid & 3) * 64;   // warp M offset
    const int nh = wid >> 2;         // N-half 0/1
    const int wn = nh * 64;          // warp N offset
    const int l4 = lane >> 2;        // groupID 0..7
    const int lc = lane & 3;         // tid-in-group 0..3

    const __half* gZ = g_Zh;
    const __half* gE = g_Eh;

    // candidate lists: 8 rows per thread (4 m-tiles x 2 halves), top-2 each
    float cv0[8], cv1[8];
    int   ci0[8], ci1[8];
#pragma unroll
    for (int r = 0; r < 8; r++) { cv0[r] = 3.4e38f; cv1[r] = 3.4e38f; ci0[r] = 0; ci1[r] = 0; }

    // fragment base offsets (half2 units)
    const int aoff = (wm + l4) * PADK + lc;
    const int boff = (wn + l4) * PADK + lc;

    // flat-chunk loader; ALWAYS commits exactly one group
    auto load_chunk = [&](int tc, int stage) {
        if (tc < TOTALC) {
            const int kc = (tc % NCHUNK) * KCH;     // in halfs
            const int n0 = (tc / NCHUNK) * CTAN;
            const uint32_t st = sbase + stage * STAGE_BYTES;
#pragma unroll
            for (int i = 0; i < 8; i++) {      // A: 256 rows x 128B = 2048 x16B
                int idx = tid + i * 256, row = idx >> 3, seg = idx & 7;
                cp16(st + row * (PADK * 4) + seg * 16,
                     gZ + (size_t)(m0 + row) * D + kc + seg * 8);
            }
#pragma unroll
            for (int i = 0; i < 4; i++) {      // B: 128 rows x 128B = 1024 x16B
                int idx = tid + i * 256, row = idx >> 3, seg = idx & 7;
                cp16(st + A_BYTES + row * (PADK * 4) + seg * 16,
                     gE + (size_t)(n0 + row) * D + kc + seg * 8);
            }
        }
        CP_COMMIT();
    };

    // prologue: chunks 0,1 -> stages 0,1
    load_chunk(0, 0);
    load_chunk(1, 1);

    float acc[4][8][4];
#pragma unroll
    for (int mt = 0; mt < 4; mt++)
#pragma unroll
        for (int nt = 0; nt < 8; nt++)
#pragma unroll
            for (int q = 0; q < 4; q++) acc[mt][nt][q] = 0.f;

    for (int tc = 0; tc < TOTALC; tc++) {
        CP_WAIT1();                 // chunk tc landed (all but newest group done)
        __syncthreads();            // visible CTA-wide + prev stage consumers done

        load_chunk(tc + 2, (tc + 2) % NSTG);

        const uint32_t* As = (const uint32_t*)(smem + (tc % NSTG) * STAGE_BYTES);
        const uint32_t* Bs = (const uint32_t*)(smem + (tc % NSTG) * STAGE_BYTES + A_BYTES);
#pragma unroll
        for (int ks = 0; ks < NK16; ks++) {
            uint32_t af[4][4], bf[8][2];
#pragma unroll
            for (int mt = 0; mt < 4; mt++) {
                int b = aoff + mt * (16 * PADK) + ks * 8;
                af[mt][0] = As[b];                 // (row g,    k 2lc..2lc+1)
                af[mt][1] = As[b + 8 * PADK];      // (row g+8,  same k)
                af[mt][2] = As[b + 4];             // (row g,    k+8)
                af[mt][3] = As[b + 8 * PADK + 4];  // (row g+8,  k+8)
            }
#pragma unroll
            for (int nt = 0; nt < 8; nt++) {
                int b = boff + nt * (8 * PADK) + ks * 8;
                bf[nt][0] = Bs[b];                 // (col g, k 2lc..2lc+1)
                bf[nt][1] = Bs[b + 4];             // (col g, k+8)
            }
#pragma unroll
            for (int mt = 0; mt < 4; mt++)
#pragma unroll
                for (int nt = 0; nt < 8; nt++)
                    mma_f16(acc[mt][nt], af[mt], bf[nt]);
        }

        // ---- iteration boundary: fold 128-code tile into per-row top-2 ----
        if ((tc % NCHUNK) == NCHUNK - 1) {
            const int n0 = (tc / NCHUNK) * CTAN;
#pragma unroll
            for (int mt = 0; mt < 4; mt++) {
#pragma unroll
                for (int h = 0; h < 2; h++) {
                    const int r = mt * 2 + h;
#pragma unroll
                    for (int nt = 0; nt < 8; nt++) {
#pragma unroll
                        for (int q = 0; q < 2; q++) {
                            int nl = wn + nt * 8 + 2 * lc + q;
                            int n = n0 + nl;
                            float dist = fmaf(-2.f, acc[mt][nt][h * 2 + q], __ldg(&g_en2[n]));
                            if (dist < cv1[r]) {
                                if (dist < cv0[r]) {
                                    cv1[r] = cv0[r]; ci1[r] = ci0[r];
                                    cv0[r] = dist;   ci0[r] = n;
                                } else {
                                    cv1[r] = dist;   ci1[r] = n;
                                }
                            }
                            acc[mt][nt][h * 2 + q] = 0.f;   // reset for next tile
                        }
                    }
                }
            }
        }
    }

    // ---- write candidates: one packed uint4 per (row, slot2); slot2 = nh*4 + lc ----
#pragma unroll
    for (int mt = 0; mt < 4; mt++) {
#pragma unroll
        for (int h = 0; h < 2; h++) {
            int r = mt * 2 + h;
            int grow = m0 + wm + mt * 16 + l4 + h * 8;
            g_cc[(size_t)grow * 8 + nh * 4 + lc] =
                make_uint4((uint32_t)ci0[r], (uint32_t)ci1[r],
                           __float_as_uint(cv0[r]), __float_as_uint(cv1[r]));
        }
    }
}

// ---------------- kernel 3: gap-gated rescore + rotation + loss partials ----------------
__global__ void k_rotate(const float* __restrict__ z, const float* __restrict__ emb,
                         float* __restrict__ out, int nrows) {
    __shared__ float s_loss[8];
    int warp = threadIdx.x >> 5;
    int lane = threadIdx.x & 31;
    int row = blockIdx.x * 8 + warp;
    float loss_w = 0.f;

    if (row < nrows) {
        const float* zr = z + (size_t)row * D;
        float zv[D / 32];
        float zz = 0.f;
#pragma unroll
        for (int j = 0; j < D / 32; j++) {
            zv[j] = zr[lane + 32 * j];
            zz = fmaf(zv[j], zv[j], zz);
        }
#pragma unroll
        for (int o = 16; o; o >>= 1) zz += __shfl_xor_sync(0xffffffffu, zz, o);

        // ---- candidates: lanes 0..15 each take one of 16 packed entries ----
        float mycv = 3.4e38f;
        int myci = 0;
        if (lane < NCAND) {
            uint4 cc = g_cc[(size_t)row * 8 + (lane >> 1)];
            myci = (int)((lane & 1) ? cc.y : cc.x) & (NCODES - 1);
            mycv = __uint_as_float((lane & 1) ? cc.w : cc.z);
        }
        // warp-reduce min (value, then index for deterministic tie)
        float bv = mycv; int bi = myci;
#pragma unroll
        for (int o = 16; o; o >>= 1) {
            float ov = __shfl_xor_sync(0xffffffffu, bv, o);
            int   oi = __shfl_xor_sync(0xffffffffu, bi, o);
            if (ov < bv || (ov == bv && oi < bi)) { bv = ov; bi = oi; }
        }
        // 2nd best: exclude the winner's slot
        float sv = (mycv == bv && myci == bi) ? 3.4e38f : mycv;
#pragma unroll
        for (int o = 16; o; o >>= 1) {
            float ov = __shfl_xor_sync(0xffffffffu, sv, o);
            sv = fminf(sv, ov);
        }

        int best_i;
        if (sv - bv >= GAP_SAFE) {
            // approx gap large vs fp16 error bound -> approx argmin == exact argmin
            best_i = bi;
        } else {
            // rare path: exact fp32 rescore of all 16
            float best_key = 3.4e38f;
            int bidx = 0x7fffffff;
            for (int c = 0; c < NCAND; c++) {
                uint4 cc = g_cc[(size_t)row * 8 + (c >> 1)];
                int ci = (int)((c & 1) ? cc.y : cc.x) & (NCODES - 1);
                const float* er = emb + (size_t)ci * D;
                float ze = 0.f;
#pragma unroll
                for (int j = 0; j < D / 32; j++) ze = fmaf(zv[j], er[lane + 32 * j], ze);
#pragma unroll
                for (int o = 16; o; o >>= 1) ze += __shfl_xor_sync(0xffffffffu, ze, o);
                float key = fmaf(-2.f, ze, g_en2[ci]);
                if (key < best_key || (key == best_key && ci < bidx)) { best_key = key; bidx = ci; }
            }
            best_i = bidx;
        }

        // load chosen code, exact stats
        const float* er = emb + (size_t)best_i * D;
        float ev[D / 32];
        float ee = 0.f, ze = 0.f;
#pragma unroll
        for (int j = 0; j < D / 32; j++) {
            ev[j] = er[lane + 32 * j];
            ee = fmaf(ev[j], ev[j], ee);
            ze = fmaf(zv[j], ev[j], ze);
        }
#pragma unroll
        for (int o = 16; o; o >>= 1) {
            ee += __shfl_xor_sync(0xffffffffu, ee, o);
            ze += __shfl_xor_sync(0xffffffffu, ze, o);
        }

        float ns_r = sqrtf(zz), nt_r = sqrtf(ee);
        float ns = fmaxf(ns_r, EPSF), nt = fmaxf(nt_r, EPSF);
        float dot_eu = zz / ns;
        float w2 = zz / (ns * ns) + ee / (nt * nt) + 2.f * ze / (ns * nt);
        float nw = fmaxf(sqrtf(w2), EPSF);
        float dot_ew = (dot_eu + ze / nt) / nw;
        float scale = nt_r / ns;
        float A = scale * (1.f - 2.f * dot_ew / (ns * nw));
        float B = scale * 2.f * (dot_eu - dot_ew / nw) / nt;

        float* orow = out + (size_t)row * D;
#pragma unroll
        for (int j = 0; j < D / 32; j++)
            orow[lane + 32 * j] = fmaf(A, zv[j], B * ev[j]);

        loss_w = zz + ee - 2.f * ze;
    }

    if (lane == 0) s_loss[warp] = loss_w;
    __syncthreads();
    if (threadIdx.x == 0) {
        float s = 0.f;
#pragma unroll
        for (int w = 0; w < 8; w++) s += s_loss[w];
        g_partial[blockIdx.x] = s;
    }
}

// ---------------- kernel 4: finalize scalar loss ----------------
__global__ void k_loss(float* __restrict__ out, int nparts, float inv_count, long long pos) {
    __shared__ float sm[256];
    float s = 0.f;
    for (int i = threadIdx.x; i < nparts; i += 256) s += g_partial[i];
    sm[threadIdx.x] = s;
    __syncthreads();
    for (int o = 128; o; o >>= 1) {
        if (threadIdx.x < o) sm[threadIdx.x] += sm[threadIdx.x + o];
        __syncthreads();
    }
    if (threadIdx.x == 0) out[pos] = 2.f * sm[0] * inv_count;
}

// ---------------- launch ----------------
extern "C" void kernel_launch(void* const* d_in, const int* in_sizes, int n_in,
                              void* d_out, int out_size) {
    const float* z   = (const float*)d_in[0];
    const float* emb = (const float*)d_in[1];
    float* out = (float*)d_out;

    int nrows  = in_sizes[0] / D;    // 32768
    int ncodes = in_sizes[1] / D;    // 8192

    cudaFuncSetAttribute(k_gemm, cudaFuncAttributeMaxDynamicSharedMemorySize, SMEM_DYN);

    int nz4 = nrows * D / 4, ne4 = ncodes * D / 4;
    k_split<<<4096, 256>>>((const float4*)z, (const float4*)emb, nz4, ne4);
    k_en2<<<(ncodes + 7) / 8, 256>>>(emb, ncodes);
    k_gemm<<<nrows / CTAM, 256, SMEM_DYN>>>();
    k_rotate<<<nrows / 8, 256>>>(z, emb, out, nrows);

    long long zq_elems = (long long)nrows * D;
    long long loss_pos = (out_size > zq_elems) ? zq_elems : (long long)out_size - 1;
    k_loss<<<1, 256>>>(out, nrows / 8, 1.f / ((float)nrows * (float)D), loss_pos);
}

// round 16
// speedup vs baseline: 1.6479x; 1.0581x over previous
#include <cuda_runtime.h>
#include <cuda_fp16.h>
#include <cstdint>

#define D 768
#define NROWS 32768
#define NCODES 8192
#define EPSF 1e-6f

// ---- GEMM tiling (fp16 operands, fp32 accumulate) ----
#define CTAM 256
#define CTAN 128
#define KCH 128                 // halfs per k-chunk = 8 m16n8k16 steps
#define NK16 (KCH / 16)         // 8
#define NCHUNK (D / KCH)        // 6
#define NITER (NCODES / CTAN)   // 64
#define TOTALC (NITER * NCHUNK) // 384 flat chunks
#define PADK 68                 // row stride in uint32; 68%32=4 -> l4*4+lc all-distinct
#define A_BYTES (CTAM * PADK * 4)       // 69632
#define B_BYTES (CTAN * PADK * 4)       // 34816
#define STAGE_BYTES (A_BYTES + B_BYTES) // 104448
#define NSTG 2
#define SMEM_DYN (NSTG * STAGE_BYTES)   // 208896
#define NCAND 16                // 8 contributing threads per row x top-2 each
#define GAP_SAFE 0.75f          // >> 2x max fp16 distance error (~0.34)

// ---------------- device scratch (no allocations allowed) ----------------
__device__ __align__(256) __half g_Zh[NROWS * D];   // fp16-rounded z
__device__ __align__(256) __half g_Eh[NCODES * D];  // fp16-rounded emb
__device__ float g_en2[NCODES];
__device__ __align__(256) uint4 g_cc[NROWS * 8];    // per row: 8 x {ci0, ci1, cv0, cv1}
__device__ float g_partial[NROWS / 8];

// ---------------- helpers ----------------
__device__ __forceinline__ uint32_t smem_u32(const void* p) {
    uint32_t a;
    asm("{ .reg .u64 t; cvta.to.shared.u64 t, %1; cvt.u32.u64 %0, t; }" : "=r"(a) : "l"(p));
    return a;
}
__device__ __forceinline__ void cp16(uint32_t dst, const void* src) {
    asm volatile("cp.async.cg.shared.global [%0], [%1], 16;" :: "r"(dst), "l"(src));
}
#define CP_COMMIT() asm volatile("cp.async.commit_group;")
#define CP_WAIT0()  asm volatile("cp.async.wait_group 0;")

__device__ __forceinline__ void mma_f16(float* c, const uint32_t* a, const uint32_t* b) {
    asm volatile(
        "mma.sync.aligned.m16n8k16.row.col.f32.f16.f16.f32 "
        "{%0,%1,%2,%3}, {%4,%5,%6,%7}, {%8,%9}, {%0,%1,%2,%3};"
        : "+f"(c[0]), "+f"(c[1]), "+f"(c[2]), "+f"(c[3])
        : "r"(a[0]), "r"(a[1]), "r"(a[2]), "r"(a[3]), "r"(b[0]), "r"(b[1]));
}

// ---------------- kernel 0: fp16 rounding of z + emb, plus emb norms ----------------
// 8 warps/block, 1 row/warp. Row < ncodes also handles the matching emb row.
__global__ void k_prep(const float* __restrict__ z, const float* __restrict__ emb,
                       int nrows, int ncodes) {
    int row = blockIdx.x * 8 + (threadIdx.x >> 5);
    int lane = threadIdx.x & 31;
    if (row < nrows) {
        const float4* s = (const float4*)(z + (size_t)row * D);
        __half2* d = (__half2*)(g_Zh + (size_t)row * D);
#pragma unroll
        for (int j = 0; j < D / 128; j++) {
            float4 v = s[lane + 32 * j];
            d[2 * (lane + 32 * j)]     = __floats2half2_rn(v.x, v.y);
            d[2 * (lane + 32 * j) + 1] = __floats2half2_rn(v.z, v.w);
        }
    }
    if (row < ncodes) {
        const float4* s = (const float4*)(emb + (size_t)row * D);
        __half2* d = (__half2*)(g_Eh + (size_t)row * D);
        float ss = 0.f;
#pragma unroll
        for (int j = 0; j < D / 128; j++) {
            float4 v = s[lane + 32 * j];
            d[2 * (lane + 32 * j)]     = __floats2half2_rn(v.x, v.y);
            d[2 * (lane + 32 * j) + 1] = __floats2half2_rn(v.z, v.w);
            ss = fmaf(v.x, v.x, ss); ss = fmaf(v.y, v.y, ss);
            ss = fmaf(v.z, v.z, ss); ss = fmaf(v.w, v.w, ss);
        }
#pragma unroll
        for (int o = 16; o; o >>= 1) ss += __shfl_xor_sync(0xffffffffu, ss, o);
        if (lane == 0) g_en2[row] = ss;
    }
}

// ---------------- kernel 1: fp16 mma.sync distance GEMM + top-2 candidates ----------------
// approx dist(m,n) = ||e_n||^2 - 2 * zh_m . eh_n   (||z||^2 constant per row -> dropped)
// 2-stage ping-pong, KCH=128: one syncthreads + one wait per chunk.
__global__ __launch_bounds__(256, 1)
void k_gemm() {
    extern __shared__ __align__(16) char smem[];
    const uint32_t sbase = smem_u32(smem);

    const int tid = threadIdx.x;
    const int wid = tid >> 5;
    const int lane = tid & 31;
    const int m0 = blockIdx.x * CTAM;
    const int wm = (wid & 3) * 64;   // warp M offset
    const int nh = wid >> 2;         // N-half 0/1
    const int wn = nh * 64;          // warp N offset
    const int l4 = lane >> 2;        // groupID 0..7
    const int lc = lane & 3;         // tid-in-group 0..3

    const __half* gZ = g_Zh;
    const __half* gE = g_Eh;

    // candidate lists: 8 rows per thread (4 m-tiles x 2 halves), top-2 each
    float cv0[8], cv1[8];
    int   ci0[8], ci1[8];
#pragma unroll
    for (int r = 0; r < 8; r++) { cv0[r] = 3.4e38f; cv1[r] = 3.4e38f; ci0[r] = 0; ci1[r] = 0; }

    // fragment base offsets (uint32 units)
    const int aoff = (wm + l4) * PADK + lc;
    const int boff = (wn + l4) * PADK + lc;

    // flat-chunk loader; ALWAYS commits exactly one group
    auto load_chunk = [&](int tc, int stage) {
        if (tc < TOTALC) {
            const int kc = (tc % NCHUNK) * KCH;     // in halfs
            const int n0 = (tc / NCHUNK) * CTAN;
            const uint32_t st = sbase + stage * STAGE_BYTES;
#pragma unroll
            for (int i = 0; i < 16; i++) {     // A: 256 rows x 16 x16B = 4096
                int idx = tid + i * 256, row = idx >> 4, seg = idx & 15;
                cp16(st + row * (PADK * 4) + seg * 16,
                     gZ + (size_t)(m0 + row) * D + kc + seg * 8);
            }
#pragma unroll
            for (int i = 0; i < 8; i++) {      // B: 128 rows x 16 x16B = 2048
                int idx = tid + i * 256, row = idx >> 4, seg = idx & 15;
                cp16(st + A_BYTES + row * (PADK * 4) + seg * 16,
                     gE + (size_t)(n0 + row) * D + kc + seg * 8);
            }
        }
        CP_COMMIT();
    };

    // prologue: chunk 0 -> stage 0
    load_chunk(0, 0);

    float acc[4][8][4];
#pragma unroll
    for (int mt = 0; mt < 4; mt++)
#pragma unroll
        for (int nt = 0; nt < 8; nt++)
#pragma unroll
            for (int q = 0; q < 4; q++) acc[mt][nt][q] = 0.f;

    for (int tc = 0; tc < TOTALC; tc++) {
        CP_WAIT0();                 // chunk tc landed
        __syncthreads();            // visible CTA-wide; prev compute done everywhere

        load_chunk(tc + 1, (tc + 1) & 1);   // overlaps with compute of tc

        const uint32_t* As = (const uint32_t*)(smem + (tc & 1) * STAGE_BYTES);
        const uint32_t* Bs = (const uint32_t*)(smem + (tc & 1) * STAGE_BYTES + A_BYTES);
#pragma unroll
        for (int ks = 0; ks < NK16; ks++) {
            uint32_t af[4][4], bf[8][2];
#pragma unroll
            for (int mt = 0; mt < 4; mt++) {
                int b = aoff + mt * (16 * PADK) + ks * 8;
                af[mt][0] = As[b];                 // (row g,    k 2lc..2lc+1)
                af[mt][1] = As[b + 8 * PADK];      // (row g+8,  same k)
                af[mt][2] = As[b + 4];             // (row g,    k+8)
                af[mt][3] = As[b + 8 * PADK + 4];  // (row g+8,  k+8)
            }
#pragma unroll
            for (int nt = 0; nt < 8; nt++) {
                int b = boff + nt * (8 * PADK) + ks * 8;
                bf[nt][0] = Bs[b];                 // (col g, k 2lc..2lc+1)
                bf[nt][1] = Bs[b + 4];             // (col g, k+8)
            }
#pragma unroll
            for (int mt = 0; mt < 4; mt++)
#pragma unroll
                for (int nt = 0; nt < 8; nt++)
                    mma_f16(acc[mt][nt], af[mt], bf[nt]);
        }

        // ---- iteration boundary: fold 128-code tile into per-row top-2 ----
        if ((tc % NCHUNK) == NCHUNK - 1) {
            const int n0 = (tc / NCHUNK) * CTAN;
#pragma unroll
            for (int mt = 0; mt < 4; mt++) {
#pragma unroll
                for (int h = 0; h < 2; h++) {
                    const int r = mt * 2 + h;
#pragma unroll
                    for (int nt = 0; nt < 8; nt++) {
#pragma unroll
                        for (int q = 0; q < 2; q++) {
                            int nl = wn + nt * 8 + 2 * lc + q;
                            int n = n0 + nl;
                            float dist = fmaf(-2.f, acc[mt][nt][h * 2 + q], __ldg(&g_en2[n]));
                            if (dist < cv1[r]) {
                                if (dist < cv0[r]) {
                                    cv1[r] = cv0[r]; ci1[r] = ci0[r];
                                    cv0[r] = dist;   ci0[r] = n;
                                } else {
                                    cv1[r] = dist;   ci1[r] = n;
                                }
                            }
                            acc[mt][nt][h * 2 + q] = 0.f;   // reset for next tile
                        }
                    }
                }
            }
        }
    }

    // ---- write candidates: one packed uint4 per (row, slot2); slot2 = nh*4 + lc ----
#pragma unroll
    for (int mt = 0; mt < 4; mt++) {
#pragma unroll
        for (int h = 0; h < 2; h++) {
            int r = mt * 2 + h;
            int grow = m0 + wm + mt * 16 + l4 + h * 8;
            g_cc[(size_t)grow * 8 + nh * 4 + lc] =
                make_uint4((uint32_t)ci0[r], (uint32_t)ci1[r],
                           __float_as_uint(cv0[r]), __float_as_uint(cv1[r]));
        }
    }
}

// ---------------- kernel 2: gap-gated rescore + rotation + loss partials ----------------
__global__ void k_rotate(const float* __restrict__ z, const float* __restrict__ emb,
                         float* __restrict__ out, int nrows) {
    __shared__ float s_loss[8];
    int warp = threadIdx.x >> 5;
    int lane = threadIdx.x & 31;
    int row = blockIdx.x * 8 + warp;
    float loss_w = 0.f;

    if (row < nrows) {
        const float* zr = z + (size_t)row * D;
        float zv[D / 32];
        float zz = 0.f;
#pragma unroll
        for (int j = 0; j < D / 32; j++) {
            zv[j] = zr[lane + 32 * j];
            zz = fmaf(zv[j], zv[j], zz);
        }
#pragma unroll
        for (int o = 16; o; o >>= 1) zz += __shfl_xor_sync(0xffffffffu, zz, o);

        // ---- candidates: lanes 0..15 each take one of 16 packed entries ----
        float mycv = 3.4e38f;
        int myci = 0;
        if (lane < NCAND) {
            uint4 cc = g_cc[(size_t)row * 8 + (lane >> 1)];
            myci = (int)((lane & 1) ? cc.y : cc.x) & (NCODES - 1);
            mycv = __uint_as_float((lane & 1) ? cc.w : cc.z);
        }
        // warp-reduce min (value, then index for deterministic tie)
        float bv = mycv; int bi = myci;
#pragma unroll
        for (int o = 16; o; o >>= 1) {
            float ov = __shfl_xor_sync(0xffffffffu, bv, o);
            int   oi = __shfl_xor_sync(0xffffffffu, bi, o);
            if (ov < bv || (ov == bv && oi < bi)) { bv = ov; bi = oi; }
        }
        // 2nd best: exclude the winner's slot
        float sv = (mycv == bv && myci == bi) ? 3.4e38f : mycv;
#pragma unroll
        for (int o = 16; o; o >>= 1) {
            float ov = __shfl_xor_sync(0xffffffffu, sv, o);
            sv = fminf(sv, ov);
        }

        int best_i;
        if (sv - bv >= GAP_SAFE) {
            // approx gap large vs fp16 error bound -> approx argmin == exact argmin
            best_i = bi;
        } else {
            // rare path: exact fp32 rescore of all 16
            float best_key = 3.4e38f;
            int bidx = 0x7fffffff;
            for (int c = 0; c < NCAND; c++) {
                uint4 cc = g_cc[(size_t)row * 8 + (c >> 1)];
                int ci = (int)((c & 1) ? cc.y : cc.x) & (NCODES - 1);
                const float* er = emb + (size_t)ci * D;
                float ze = 0.f;
#pragma unroll
                for (int j = 0; j < D / 32; j++) ze = fmaf(zv[j], er[lane + 32 * j], ze);
#pragma unroll
                for (int o = 16; o; o >>= 1) ze += __shfl_xor_sync(0xffffffffu, ze, o);
                float key = fmaf(-2.f, ze, g_en2[ci]);
                if (key < best_key || (key == best_key && ci < bidx)) { best_key = key; bidx = ci; }
            }
            best_i = bidx;
        }

        // load chosen code, exact stats
        const float* er = emb + (size_t)best_i * D;
        float ev[D / 32];
        float ee = 0.f, ze = 0.f;
#pragma unroll
        for (int j = 0; j < D / 32; j++) {
            ev[j] = er[lane + 32 * j];
            ee = fmaf(ev[j], ev[j], ee);
            ze = fmaf(zv[j], ev[j], ze);
        }
#pragma unroll
        for (int o = 16; o; o >>= 1) {
            ee += __shfl_xor_sync(0xffffffffu, ee, o);
            ze += __shfl_xor_sync(0xffffffffu, ze, o);
        }

        float ns_r = sqrtf(zz), nt_r = sqrtf(ee);
        float ns = fmaxf(ns_r, EPSF), nt = fmaxf(nt_r, EPSF);
        float dot_eu = zz / ns;
        float w2 = zz / (ns * ns) + ee / (nt * nt) + 2.f * ze / (ns * nt);
        float nw = fmaxf(sqrtf(w2), EPSF);
        float dot_ew = (dot_eu + ze / nt) / nw;
        float scale = nt_r / ns;
        float A = scale * (1.f - 2.f * dot_ew / (ns * nw));
        float B = scale * 2.f * (dot_eu - dot_ew / nw) / nt;

        float* orow = out + (size_t)row * D;
#pragma unroll
        for (int j = 0; j < D / 32; j++)
            orow[lane + 32 * j] = fmaf(A, zv[j], B * ev[j]);

        loss_w = zz + ee - 2.f * ze;
    }

    if (lane == 0) s_loss[warp] = loss_w;
    __syncthreads();
    if (threadIdx.x == 0) {
        float s = 0.f;
#pragma unroll
        for (int w = 0; w < 8; w++) s += s_loss[w];
        g_partial[blockIdx.x] = s;
    }
}

// ---------------- kernel 3: finalize scalar loss ----------------
__global__ void k_loss(float* __restrict__ out, int nparts, float inv_count, long long pos) {
    __shared__ float sm[256];
    float s = 0.f;
    for (int i = threadIdx.x; i < nparts; i += 256) s += g_partial[i];
    sm[threadIdx.x] = s;
    __syncthreads();
    for (int o = 128; o; o >>= 1) {
        if (threadIdx.x < o) sm[threadIdx.x] += sm[threadIdx.x + o];
        __syncthreads();
    }
    if (threadIdx.x == 0) out[pos] = 2.f * sm[0] * inv_count;
}

// ---------------- launch ----------------
extern "C" void kernel_launch(void* const* d_in, const int* in_sizes, int n_in,
                              void* d_out, int out_size) {
    const float* z   = (const float*)d_in[0];
    const float* emb = (const float*)d_in[1];
    float* out = (float*)d_out;

    int nrows  = in_sizes[0] / D;    // 32768
    int ncodes = in_sizes[1] / D;    // 8192

    cudaFuncSetAttribute(k_gemm, cudaFuncAttributeMaxDynamicSharedMemorySize, SMEM_DYN);

    k_prep<<<(nrows + 7) / 8, 256>>>(z, emb, nrows, ncodes);
    k_gemm<<<nrows / CTAM, 256, SMEM_DYN>>>();
    k_rotate<<<nrows / 8, 256>>>(z, emb, out, nrows);

    long long zq_elems = (long long)nrows * D;
    long long loss_pos = (out_size > zq_elems) ? zq_elems : (long long)out_size - 1;
    k_loss<<<1, 256>>>(out, nrows / 8, 1.f / ((float)nrows * (float)D), loss_pos);
}